// round 7
// baseline (speedup 1.0000x reference)
#include <cuda_runtime.h>
#include <cuda_bf16.h>
#include <cstdint>

#define N_NODES 100000
#define E_EDGES 500000

// ---------------------------------------------------------------------------
// Device scratch
// ---------------------------------------------------------------------------
__device__ float g_UV[(size_t)N_NODES * 512];   // per node: U[0:256], V[256:512]
__device__ uint4 g_nBhi4[16384];                // node B: 8 chunks x 128x128 bf16
__device__ uint4 g_nBlo4[16384];
__device__ uint4 g_eBhi4[4096];                 // edge B (W2): 2 chunks x 128x128 bf16
__device__ uint4 g_eBlo4[4096];
__device__ int   g_idx64;

#define CHUNK_U4 2048   // 128*128 bf16 = 32768 B = 2048 uint4

#define PITCH_A 528     // A row: 256 bf16 + 8 pad
#define PITCH_B 272     // B row: 128 bf16 + 8 pad
#define A_TILE  (128 * PITCH_A)   // 67584
#define B_TILE  (128 * PITCH_B)   // 34816

// edge smem layout (bytes)
#define E_SRC  0
#define E_DST  512
#define E_AHI  1024
#define E_ALO  (E_AHI + A_TILE)
#define E_BHI  (E_ALO + A_TILE)
#define E_BLO  (E_BHI + B_TILE)
#define SM_EDGE (E_BLO + B_TILE)    // 205824

// node smem layout
#define N_AHI  0
#define N_ALO  (N_AHI + A_TILE)
#define N_BHI  (N_ALO + A_TILE)
#define N_BLO  (N_BHI + B_TILE)
#define SM_NODE (N_BLO + B_TILE)    // 204800

__device__ __forceinline__ uint32_t smem_u32(const void* p) {
    uint32_t a;
    asm("{ .reg .u64 t; cvta.to.shared.u64 t, %1; cvt.u32.u64 %0, t; }" : "=r"(a) : "l"(p));
    return a;
}

__device__ __forceinline__ void ldsm_x4(uint32_t* r, uint32_t addr) {
    asm volatile("ldmatrix.sync.aligned.m8n8.x4.shared.b16 {%0,%1,%2,%3}, [%4];"
                 : "=r"(r[0]), "=r"(r[1]), "=r"(r[2]), "=r"(r[3]) : "r"(addr));
}

__device__ __forceinline__ void mma16816(float* d, const uint32_t* a, const uint32_t* b) {
    asm volatile(
        "mma.sync.aligned.m16n8k16.row.col.f32.bf16.bf16.f32 "
        "{%0,%1,%2,%3},{%4,%5,%6,%7},{%8,%9},{%0,%1,%2,%3};"
        : "+f"(d[0]), "+f"(d[1]), "+f"(d[2]), "+f"(d[3])
        : "r"(a[0]), "r"(a[1]), "r"(a[2]), "r"(a[3]), "r"(b[0]), "r"(b[1]));
}

__device__ __forceinline__ void cpasync16(uint32_t saddr, const void* g) {
    asm volatile("cp.async.ca.shared.global [%0], [%1], 16;" :: "r"(saddr), "l"(g));
}
__device__ __forceinline__ void cp_commit() { asm volatile("cp.async.commit_group;"); }
__device__ __forceinline__ void cp_wait0()  { asm volatile("cp.async.wait_group 0;" ::: "memory"); }

__device__ __forceinline__ void split2(float a, float b, uint32_t& hi, uint32_t& lo) {
    __nv_bfloat16 ah = __float2bfloat16_rn(a);
    __nv_bfloat16 bh = __float2bfloat16_rn(b);
    __nv_bfloat16 al = __float2bfloat16_rn(a - __bfloat162float(ah));
    __nv_bfloat16 bl = __float2bfloat16_rn(b - __bfloat162float(bh));
    hi = (uint32_t)__bfloat16_as_ushort(ah) | ((uint32_t)__bfloat16_as_ushort(bh) << 16);
    lo = (uint32_t)__bfloat16_as_ushort(al) | ((uint32_t)__bfloat16_as_ushort(bl) << 16);
}

// ---------------------------------------------------------------------------
// detect edge_index dtype (int64 vs int32)
// ---------------------------------------------------------------------------
__global__ void detect_kernel(const unsigned* __restrict__ ei) {
    if (threadIdx.x == 0 && blockIdx.x == 0) {
        int ok = 1;
        #pragma unroll 1
        for (int i = 0; i < 256; i++)
            if (ei[2 * i + 1] != 0u) { ok = 0; break; }
        g_idx64 = ok;
    }
}

// ---------------------------------------------------------------------------
// prep: split weights into bf16 hi/lo chunk blobs [chunk][row][k] (128x128)
// ---------------------------------------------------------------------------
__global__ void prep_kernel(const float* __restrict__ W1, const float* __restrict__ W2) {
    int idx = blockIdx.x * blockDim.x + threadIdx.x;
    float v;
    uint32_t off;
    __nv_bfloat16 *dh, *dl;
    if (idx < 131072) {
        int j = idx >> 8, k = idx & 255;
        v = (j < 256) ? W1[j * 512 + k] : W1[(j - 256) * 512 + 256 + k];
        int nc = j >> 7, row = j & 127, kc = k >> 7, kp = k & 127;
        off = (uint32_t)(kc * 4 + nc) * 16384u + row * 128 + kp;
        dh = (__nv_bfloat16*)g_nBhi4; dl = (__nv_bfloat16*)g_nBlo4;
    } else {
        int e = idx - 131072;
        if (e >= 32768) return;
        int n = e >> 8, k = e & 255;
        v = W2[n * 256 + k];
        int kc = k >> 7, kp = k & 127;
        off = (uint32_t)kc * 16384u + n * 128 + kp;
        dh = (__nv_bfloat16*)g_eBhi4; dl = (__nv_bfloat16*)g_eBlo4;
    }
    __nv_bfloat16 h = __float2bfloat16_rn(v);
    dh[off] = h;
    dl[off] = __float2bfloat16_rn(v - __bfloat162float(h));
}

// ---------------------------------------------------------------------------
// helpers
// ---------------------------------------------------------------------------
// async-copy one 128x128 bf16 chunk (hi+lo) into smem B tiles; 512 threads
__device__ __forceinline__ void load_B_async(uint32_t smB_hi, uint32_t smB_lo,
                                             const uint4* srcH, const uint4* srcL, int tid) {
    #pragma unroll
    for (int i = 0; i < 4; i++) {
        int idx = i * 512 + tid;          // 0..2047
        int row = idx >> 4, c = idx & 15;
        uint32_t d = row * PITCH_B + c * 16;
        cpasync16(smB_hi + d, srcH + idx);
        cpasync16(smB_lo + d, srcL + idx);
    }
    cp_commit();
}

// 8 k-steps of 3-pass bf16 mma over one 128-k chunk; warp tile 32(M)x32(N)
__device__ __forceinline__ void mma_chunk(float d[2][4][4],
                                          uint32_t aHi, uint32_t aLo,
                                          uint32_t bHi, uint32_t bLo) {
    #pragma unroll 1
    for (int ks = 0; ks < 8; ks++) {
        uint32_t Ah[2][4], Al[2][4], Bh[2][4], Bl[2][4];
        #pragma unroll
        for (int f = 0; f < 2; f++) {
            ldsm_x4(Ah[f], aHi + f * (16 * PITCH_A) + ks * 32);
            ldsm_x4(Al[f], aLo + f * (16 * PITCH_A) + ks * 32);
        }
        #pragma unroll
        for (int gp = 0; gp < 2; gp++) {
            ldsm_x4(Bh[gp], bHi + gp * (16 * PITCH_B) + ks * 32);
            ldsm_x4(Bl[gp], bLo + gp * (16 * PITCH_B) + ks * 32);
        }
        #pragma unroll
        for (int f = 0; f < 2; f++)
            #pragma unroll
            for (int g = 0; g < 4; g++) {
                const uint32_t* bh = &Bh[g >> 1][(g & 1) * 2];
                const uint32_t* bl = &Bl[g >> 1][(g & 1) * 2];
                mma16816(d[f][g], Ah[f], bh);
                mma16816(d[f][g], Ah[f], bl);
                mma16816(d[f][g], Al[f], bh);
            }
    }
}

__device__ __forceinline__ uint32_t a_lane_base(uint32_t smA, int wm, int lane) {
    int row = wm * 32 + (lane & 7) + ((lane >> 3) & 1) * 8;
    return smA + row * PITCH_A + ((lane >> 4) & 1) * 16;
}
__device__ __forceinline__ uint32_t b_lane_base(uint32_t smB, int wn, int lane) {
    int n = wn * 32 + (lane & 7) + ((lane >> 4) & 1) * 8;
    return smB + n * PITCH_B + ((lane >> 3) & 1) * 16;
}

// ---------------------------------------------------------------------------
// node kernel: 128-node tiles, 512 threads (16 warps, 4x4), full-K A resident
// ---------------------------------------------------------------------------
__global__ void __launch_bounds__(512, 1) node_mma(const float* __restrict__ Z) {
    extern __shared__ char sm[];
    const uint32_t smb = smem_u32(sm);
    const int tid = threadIdx.x, lane = tid & 31, wid = tid >> 5;
    const int wm = wid & 3, wn = wid >> 2;
    const int mbase = blockIdx.x * 128;

    // prefetch first B chunk while staging A
    load_B_async(smb + N_BHI, smb + N_BLO, g_nBhi4, g_nBlo4, tid);

    // --- stage A: full K=256, split to bf16 hi/lo ---
    {
        const int row = tid >> 2;            // 0..127
        const int koff = (tid & 3) * 64;     // float offset
        int gr = min(mbase + row, N_NODES - 1);
        const float* zr = Z + (size_t)gr * 256 + koff;
        char* ah = sm + N_AHI + row * PITCH_A + koff * 2;
        char* al = sm + N_ALO + row * PITCH_A + koff * 2;
        #pragma unroll
        for (int i = 0; i < 16; i++) {
            float4 z4 = *(const float4*)(zr + i * 4);
            uint32_t h0, l0, h1, l1;
            split2(z4.x, z4.y, h0, l0);
            split2(z4.z, z4.w, h1, l1);
            *(uint2*)(ah + i * 8) = make_uint2(h0, h1);
            *(uint2*)(al + i * 8) = make_uint2(l0, l1);
        }
    }

    const uint32_t aHi = a_lane_base(smb + N_AHI, wm, lane);
    const uint32_t aLo = a_lane_base(smb + N_ALO, wm, lane);
    const uint32_t bHi = b_lane_base(smb + N_BHI, wn, lane);
    const uint32_t bLo = b_lane_base(smb + N_BLO, wn, lane);

    #pragma unroll 1
    for (int nc = 0; nc < 4; nc++) {
        float d[2][4][4];
        #pragma unroll
        for (int f = 0; f < 2; f++)
            #pragma unroll
            for (int g = 0; g < 4; g++)
                #pragma unroll
                for (int c = 0; c < 4; c++) d[f][g][c] = 0.f;

        #pragma unroll 1
        for (int kc = 0; kc < 2; kc++) {
            cp_wait0();
            __syncthreads();
            mma_chunk(d, aHi + kc * 256, aLo + kc * 256, bHi, bLo);
            __syncthreads();
            // prefetch next B chunk (order: kc=0,1 per nc)
            int nn = nc + (kc == 1 ? 1 : 0);
            int nk = (kc == 1) ? 0 : 1;
            if (nn < 4)
                load_B_async(smb + N_BHI, smb + N_BLO,
                             g_nBhi4 + (nk * 4 + nn) * CHUNK_U4,
                             g_nBlo4 + (nk * 4 + nn) * CHUNK_U4, tid);
        }

        // epilogue: 128x128 block to g_UV
        #pragma unroll
        for (int g = 0; g < 4; g++) {
            int col = nc * 128 + wn * 32 + g * 8 + (lane & 3) * 2;
            #pragma unroll
            for (int f = 0; f < 2; f++) {
                int r0 = mbase + wm * 32 + f * 16 + (lane >> 2);
                if (r0 < N_NODES)
                    *(float2*)(g_UV + (size_t)r0 * 512 + col) =
                        make_float2(d[f][g][0], d[f][g][1]);
                int r1 = r0 + 8;
                if (r1 < N_NODES)
                    *(float2*)(g_UV + (size_t)r1 * 512 + col) =
                        make_float2(d[f][g][2], d[f][g][3]);
            }
        }
    }
}

// ---------------------------------------------------------------------------
// edge kernel: 128-edge tiles, 512 threads, full-K A resident, B via cp.async
// ---------------------------------------------------------------------------
__global__ void __launch_bounds__(512, 1) edge_mma(const void* __restrict__ EI,
                                                   const float* __restrict__ b1,
                                                   const float* __restrict__ b2,
                                                   float* __restrict__ out) {
    extern __shared__ char sm[];
    const uint32_t smb = smem_u32(sm);
    int* ssrc = (int*)(sm + E_SRC);
    int* sdst = (int*)(sm + E_DST);
    const int tid = threadIdx.x, lane = tid & 31, wid = tid >> 5;
    const int wm = wid & 3, wn = wid >> 2;
    const int ebase = blockIdx.x * 128;

    // prefetch first B chunk immediately
    load_B_async(smb + E_BHI, smb + E_BLO, g_eBhi4, g_eBlo4, tid);

    if (tid < 128) {
        int e = ebase + tid;
        long long s = 0, dd = 0;
        if (e < E_EDGES) {
            if (g_idx64) {
                const long long* p = (const long long*)EI;
                s = p[e]; dd = p[E_EDGES + e];
            } else {
                const int* p = (const int*)EI;
                s = p[e]; dd = p[E_EDGES + e];
            }
        }
        ssrc[tid] = min(max((int)s, 0), N_NODES - 1);
        sdst[tid] = min(max((int)dd, 0), N_NODES - 1);
    }
    __syncthreads();

    // --- stage A: gather U[src]+V[dst]+b1, relu, split, full K=256 ---
    {
        const int row = tid >> 2;            // 0..127
        const int koff = (tid & 3) * 64;     // floats
        const float* Ur = g_UV + (size_t)ssrc[row] * 512 + koff;
        const float* Vr = g_UV + (size_t)sdst[row] * 512 + 256 + koff;
        const float* Br = b1 + koff;
        char* ah = sm + E_AHI + row * PITCH_A + koff * 2;
        char* al = sm + E_ALO + row * PITCH_A + koff * 2;
        #pragma unroll
        for (int i = 0; i < 16; i++) {
            float4 u4 = *(const float4*)(Ur + i * 4);
            float4 v4 = *(const float4*)(Vr + i * 4);
            float4 c4 = *(const float4*)(Br + i * 4);
            float h0 = fmaxf(u4.x + v4.x + c4.x, 0.f);
            float h1 = fmaxf(u4.y + v4.y + c4.y, 0.f);
            float h2 = fmaxf(u4.z + v4.z + c4.z, 0.f);
            float h3 = fmaxf(u4.w + v4.w + c4.w, 0.f);
            uint32_t H0, L0, H1, L1;
            split2(h0, h1, H0, L0);
            split2(h2, h3, H1, L1);
            *(uint2*)(ah + i * 8) = make_uint2(H0, H1);
            *(uint2*)(al + i * 8) = make_uint2(L0, L1);
        }
    }

    const uint32_t aHi = a_lane_base(smb + E_AHI, wm, lane);
    const uint32_t aLo = a_lane_base(smb + E_ALO, wm, lane);
    const uint32_t bHi = b_lane_base(smb + E_BHI, wn, lane);
    const uint32_t bLo = b_lane_base(smb + E_BLO, wn, lane);

    float d[2][4][4];
    #pragma unroll
    for (int f = 0; f < 2; f++)
        #pragma unroll
        for (int g = 0; g < 4; g++)
            #pragma unroll
            for (int c = 0; c < 4; c++) d[f][g][c] = 0.f;

    #pragma unroll 1
    for (int kc = 0; kc < 2; kc++) {
        cp_wait0();
        __syncthreads();
        mma_chunk(d, aHi + kc * 256, aLo + kc * 256, bHi, bLo);
        __syncthreads();
        if (kc == 0)
            load_B_async(smb + E_BHI, smb + E_BLO,
                         g_eBhi4 + CHUNK_U4, g_eBlo4 + CHUNK_U4, tid);
    }

    // epilogue: + b2, write 128x128
    #pragma unroll
    for (int g = 0; g < 4; g++) {
        int col = wn * 32 + g * 8 + (lane & 3) * 2;
        float bx = b2[col], by = b2[col + 1];
        #pragma unroll
        for (int f = 0; f < 2; f++) {
            int r0 = ebase + wm * 32 + f * 16 + (lane >> 2);
            if (r0 < E_EDGES)
                *(float2*)(out + (size_t)r0 * 128 + col) =
                    make_float2(d[f][g][0] + bx, d[f][g][1] + by);
            int r1 = r0 + 8;
            if (r1 < E_EDGES)
                *(float2*)(out + (size_t)r1 * 128 + col) =
                    make_float2(d[f][g][2] + bx, d[f][g][3] + by);
        }
    }
}

// ---------------------------------------------------------------------------
// launch — inputs resolved by unique element counts
// ---------------------------------------------------------------------------
extern "C" void kernel_launch(void* const* d_in, const int* in_sizes, int n_in,
                              void* d_out, int out_size) {
    const float* z = nullptr;
    const void* ei = nullptr;
    const float* W1 = nullptr;
    const float* b1 = nullptr;
    const float* W2 = nullptr;
    const float* b2 = nullptr;
    for (int i = 0; i < n_in; i++) {
        switch (in_sizes[i]) {
            case 25600000: z = (const float*)d_in[i]; break;
            case 1000000:  ei = d_in[i];              break;
            case 131072:   W1 = (const float*)d_in[i]; break;
            case 256:      b1 = (const float*)d_in[i]; break;
            case 32768:    W2 = (const float*)d_in[i]; break;
            case 128:      b2 = (const float*)d_in[i]; break;
            default: break;
        }
    }
    float* out = (float*)d_out;

    cudaFuncSetAttribute(node_mma, cudaFuncAttributeMaxDynamicSharedMemorySize, SM_NODE);
    cudaFuncSetAttribute(edge_mma, cudaFuncAttributeMaxDynamicSharedMemorySize, SM_EDGE);

    detect_kernel<<<1, 32>>>((const unsigned*)ei);
    prep_kernel<<<640, 256>>>(W1, W2);
    node_mma<<<(N_NODES + 127) / 128, 512, SM_NODE>>>(z);
    edge_mma<<<(E_EDGES + 127) / 128, 512, SM_EDGE>>>(ei, b1, b2, out);
}

// round 8
// speedup vs baseline: 1.5013x; 1.5013x over previous
#include <cuda_runtime.h>
#include <cuda_bf16.h>
#include <cstdint>

#define N_NODES 100000
#define E_EDGES 500000

// ---------------------------------------------------------------------------
// Device scratch
// ---------------------------------------------------------------------------
__device__ float g_UV[(size_t)N_NODES * 512];   // per node: U[0:256], V[256:512]
__device__ uint4 g_nBhi4[16384];                // node B: 8 chunks x 128x128 bf16
__device__ uint4 g_nBlo4[16384];
__device__ uint4 g_eBhi4[4096];                 // edge B (W2): 2 chunks x 128x128 bf16
__device__ uint4 g_eBlo4[4096];
__device__ int   g_idx64;

#define CHUNK_U4 2048   // 128*128 bf16 = 32768 B = 2048 uint4

// smem layout (bytes)
#define OFF_SRC  0
#define OFF_DST  512
#define OFF_AHI  1024
#define OFF_ALO  (1024 + 67584)
#define OFF_BHI  (1024 + 2 * 67584)
#define OFF_BLO  (1024 + 2 * 67584 + 34816)
#define SM_BYTES (1024 + 2 * 67584 + 2 * 34816)   // 205824
#define PITCH_A  528    // bytes per A row (264 bf16: 256 + 8 pad)
#define PITCH_B  272    // bytes per B row (136 bf16: 128 + 8 pad)
#define STG_PITCH 132   // floats per staged output row (128 + 4 pad)

__device__ __forceinline__ uint32_t smem_u32(const void* p) {
    uint32_t a;
    asm("{ .reg .u64 t; cvta.to.shared.u64 t, %1; cvt.u32.u64 %0, t; }" : "=r"(a) : "l"(p));
    return a;
}

__device__ __forceinline__ void ldsm_x4(uint32_t* r, uint32_t addr) {
    asm volatile("ldmatrix.sync.aligned.m8n8.x4.shared.b16 {%0,%1,%2,%3}, [%4];"
                 : "=r"(r[0]), "=r"(r[1]), "=r"(r[2]), "=r"(r[3]) : "r"(addr));
}

__device__ __forceinline__ void mma16816(float* d, const uint32_t* a, const uint32_t* b) {
    asm volatile(
        "mma.sync.aligned.m16n8k16.row.col.f32.bf16.bf16.f32 "
        "{%0,%1,%2,%3},{%4,%5,%6,%7},{%8,%9},{%0,%1,%2,%3};"
        : "+f"(d[0]), "+f"(d[1]), "+f"(d[2]), "+f"(d[3])
        : "r"(a[0]), "r"(a[1]), "r"(a[2]), "r"(a[3]), "r"(b[0]), "r"(b[1]));
}

__device__ __forceinline__ void cpasync16(uint32_t saddr, const void* g) {
    asm volatile("cp.async.ca.shared.global [%0], [%1], 16;" :: "r"(saddr), "l"(g));
}
__device__ __forceinline__ void cp_commit() { asm volatile("cp.async.commit_group;"); }
__device__ __forceinline__ void cp_wait0()  { asm volatile("cp.async.wait_group 0;" ::: "memory"); }

__device__ __forceinline__ void split2(float a, float b, uint32_t& hi, uint32_t& lo) {
    __nv_bfloat16 ah = __float2bfloat16_rn(a);
    __nv_bfloat16 bh = __float2bfloat16_rn(b);
    __nv_bfloat16 al = __float2bfloat16_rn(a - __bfloat162float(ah));
    __nv_bfloat16 bl = __float2bfloat16_rn(b - __bfloat162float(bh));
    hi = (uint32_t)__bfloat16_as_ushort(ah) | ((uint32_t)__bfloat16_as_ushort(bh) << 16);
    lo = (uint32_t)__bfloat16_as_ushort(al) | ((uint32_t)__bfloat16_as_ushort(bl) << 16);
}

// ---------------------------------------------------------------------------
// detect edge_index dtype (int64 vs int32)
// ---------------------------------------------------------------------------
__global__ void detect_kernel(const unsigned* __restrict__ ei) {
    if (threadIdx.x == 0 && blockIdx.x == 0) {
        int ok = 1;
        #pragma unroll 1
        for (int i = 0; i < 256; i++)
            if (ei[2 * i + 1] != 0u) { ok = 0; break; }
        g_idx64 = ok;
    }
}

// ---------------------------------------------------------------------------
// prep: split weights into bf16 hi/lo chunk blobs [chunk][row][k] (128x128)
// ---------------------------------------------------------------------------
__global__ void prep_kernel(const float* __restrict__ W1, const float* __restrict__ W2) {
    int idx = blockIdx.x * blockDim.x + threadIdx.x;
    float v;
    uint32_t off;
    __nv_bfloat16 *dh, *dl;
    if (idx < 131072) {
        int j = idx >> 8, k = idx & 255;
        v = (j < 256) ? W1[j * 512 + k] : W1[(j - 256) * 512 + 256 + k];
        int nc = j >> 7, row = j & 127, kc = k >> 7, kp = k & 127;
        off = (uint32_t)(kc * 4 + nc) * 16384u + row * 128 + kp;
        dh = (__nv_bfloat16*)g_nBhi4; dl = (__nv_bfloat16*)g_nBlo4;
    } else {
        int e = idx - 131072;
        if (e >= 32768) return;
        int n = e >> 8, k = e & 255;
        v = W2[n * 256 + k];
        int kc = k >> 7, kp = k & 127;
        off = (uint32_t)kc * 16384u + n * 128 + kp;
        dh = (__nv_bfloat16*)g_eBhi4; dl = (__nv_bfloat16*)g_eBlo4;
    }
    __nv_bfloat16 h = __float2bfloat16_rn(v);
    dh[off] = h;
    dl[off] = __float2bfloat16_rn(v - __bfloat162float(h));
}

// ---------------------------------------------------------------------------
// helpers
// ---------------------------------------------------------------------------
// async prefetch one 128x128 bf16 chunk (hi+lo) into smem B tiles; 256 threads
__device__ __forceinline__ void load_B_async(uint32_t smB_hi, uint32_t smB_lo,
                                             const uint4* srcH, const uint4* srcL, int tid) {
    #pragma unroll
    for (int i = 0; i < 8; i++) {
        int idx = i * 256 + tid;          // 0..2047
        int row = idx >> 4, c = idx & 15;
        uint32_t d = row * PITCH_B + c * 16;
        cpasync16(smB_hi + d, srcH + idx);
        cpasync16(smB_lo + d, srcL + idx);
    }
    cp_commit();
}

// 8 k-steps of 3-pass bf16 mma over one 128-k chunk; warp tile 64(M)x32(N)
__device__ __forceinline__ void mma_chunk(float d[4][4][4],
                                          uint32_t aHiBase, uint32_t aLoBase,
                                          uint32_t bHiBase, uint32_t bLoBase) {
    #pragma unroll 1
    for (int ks = 0; ks < 8; ks++) {
        uint32_t Ah[4][4], Al[4][4], Bh[2][4], Bl[2][4];
        #pragma unroll
        for (int f = 0; f < 4; f++) {
            ldsm_x4(Ah[f], aHiBase + f * (16 * PITCH_A) + ks * 32);
            ldsm_x4(Al[f], aLoBase + f * (16 * PITCH_A) + ks * 32);
        }
        #pragma unroll
        for (int gp = 0; gp < 2; gp++) {
            ldsm_x4(Bh[gp], bHiBase + gp * (16 * PITCH_B) + ks * 32);
            ldsm_x4(Bl[gp], bLoBase + gp * (16 * PITCH_B) + ks * 32);
        }
        #pragma unroll
        for (int f = 0; f < 4; f++)
            #pragma unroll
            for (int g = 0; g < 4; g++) {
                const uint32_t* bh = &Bh[g >> 1][(g & 1) * 2];
                const uint32_t* bl = &Bl[g >> 1][(g & 1) * 2];
                mma16816(d[f][g], Ah[f], bh);
                mma16816(d[f][g], Ah[f], bl);
                mma16816(d[f][g], Al[f], bh);
            }
    }
}

__device__ __forceinline__ uint32_t a_lane_base(uint32_t smA, int wm, int lane) {
    int row = wm * 64 + (lane & 7) + ((lane >> 3) & 1) * 8;
    return smA + row * PITCH_A + ((lane >> 4) & 1) * 16;
}
__device__ __forceinline__ uint32_t b_lane_base(uint32_t smB, int wn, int lane) {
    int n = wn * 32 + (lane & 7) + ((lane >> 4) & 1) * 8;
    return smB + n * PITCH_B + ((lane >> 3) & 1) * 16;
}

// stage warp accumulators into fp32 smem tile [128][STG_PITCH]
__device__ __forceinline__ void stage_acc(float* stg, float d[4][4][4],
                                          int wm, int wn, int lane) {
    #pragma unroll
    for (int g = 0; g < 4; g++) {
        int col = wn * 32 + g * 8 + (lane & 3) * 2;
        #pragma unroll
        for (int f = 0; f < 4; f++) {
            int r0 = wm * 64 + f * 16 + (lane >> 2);
            *(float2*)(stg + r0 * STG_PITCH + col) = make_float2(d[f][g][0], d[f][g][1]);
            *(float2*)(stg + (r0 + 8) * STG_PITCH + col) = make_float2(d[f][g][2], d[f][g][3]);
        }
    }
}

// ---------------------------------------------------------------------------
// node kernel: UV[tile of 128 nodes, 512] = Z @ B^T (3-pass bf16 mma.sync)
// ---------------------------------------------------------------------------
__global__ void __launch_bounds__(256, 1) node_mma(const float* __restrict__ Z) {
    extern __shared__ char sm[];
    const uint32_t smb = smem_u32(sm);
    const int tid = threadIdx.x, lane = tid & 31, wid = tid >> 5;
    const int wm = wid & 1, wn = wid >> 1;
    const int mbase = blockIdx.x * 128;

    // prefetch first B chunk (nc=0, kc=0) — overlaps the A staging below
    load_B_async(smb + OFF_BHI, smb + OFF_BLO, g_nBhi4, g_nBlo4, tid);

    // --- stage A: load Z rows, split to bf16 hi/lo, full K=256 resident ---
    {
        const int lrow = tid >> 3;          // 0..31 per sweep
        const int lk = (tid & 7) * 4;       // float offset
        #pragma unroll 1
        for (int s = 0; s < 4; s++) {
            int row = s * 32 + lrow;
            int gr = min(mbase + row, N_NODES - 1);
            const float* zr = Z + (size_t)gr * 256;
            char* ah = sm + OFF_AHI + row * PITCH_A;
            char* al = sm + OFF_ALO + row * PITCH_A;
            #pragma unroll
            for (int i = 0; i < 8; i++) {
                int k = lk + i * 32;
                float4 z4 = *(const float4*)(zr + k);
                uint32_t h0, l0, h1, l1;
                split2(z4.x, z4.y, h0, l0);
                split2(z4.z, z4.w, h1, l1);
                *(uint2*)(ah + k * 2) = make_uint2(h0, h1);
                *(uint2*)(al + k * 2) = make_uint2(l0, l1);
            }
        }
    }

    const uint32_t aHi = a_lane_base(smb + OFF_AHI, wm, lane);
    const uint32_t aLo = a_lane_base(smb + OFF_ALO, wm, lane);
    const uint32_t bHi = b_lane_base(smb + OFF_BHI, wn, lane);
    const uint32_t bLo = b_lane_base(smb + OFF_BLO, wn, lane);
    float* stg = (float*)(sm + OFF_BHI);

    #pragma unroll 1
    for (int nc = 0; nc < 4; nc++) {
        float d[4][4][4];
        #pragma unroll
        for (int f = 0; f < 4; f++)
            #pragma unroll
            for (int g = 0; g < 4; g++)
                #pragma unroll
                for (int c = 0; c < 4; c++) d[f][g][c] = 0.f;

        #pragma unroll 1
        for (int kc = 0; kc < 2; kc++) {
            cp_wait0();
            __syncthreads();
            mma_chunk(d, aHi + kc * 256, aLo + kc * 256, bHi, bLo);
            __syncthreads();
            if (kc == 0)    // prefetch second k-chunk of this nc
                load_B_async(smb + OFF_BHI, smb + OFF_BLO,
                             g_nBhi4 + (1 * 4 + nc) * CHUNK_U4,
                             g_nBlo4 + (1 * 4 + nc) * CHUNK_U4, tid);
        }

        // --- staged, coalesced epilogue (B area is dead now) ---
        stage_acc(stg, d, wm, wn, lane);
        __syncthreads();
        {
            const int c = (tid & 31) * 4;
            #pragma unroll
            for (int i = 0; i < 16; i++) {
                int idx = i * 256 + tid;
                int row = idx >> 5;
                int gr = mbase + row;
                if (gr < N_NODES) {
                    float4 v = *(const float4*)(stg + row * STG_PITCH + c);
                    *(float4*)(g_UV + (size_t)gr * 512 + nc * 128 + c) = v;
                }
            }
        }
        __syncthreads();
        if (nc < 3)     // prefetch next nc's first k-chunk
            load_B_async(smb + OFF_BHI, smb + OFF_BLO,
                         g_nBhi4 + (0 * 4 + nc + 1) * CHUNK_U4,
                         g_nBlo4 + (0 * 4 + nc + 1) * CHUNK_U4, tid);
    }
}

// ---------------------------------------------------------------------------
// edge kernel: out[128 edges, 128] = relu(U[src]+V[dst]+b1) @ W2^T + b2
// ---------------------------------------------------------------------------
__global__ void __launch_bounds__(256, 1) edge_mma(const void* __restrict__ EI,
                                                   const float* __restrict__ b1,
                                                   const float* __restrict__ b2,
                                                   float* __restrict__ out) {
    extern __shared__ char sm[];
    const uint32_t smb = smem_u32(sm);
    int* ssrc = (int*)(sm + OFF_SRC);
    int* sdst = (int*)(sm + OFF_DST);
    const int tid = threadIdx.x, lane = tid & 31, wid = tid >> 5;
    const int wm = wid & 1, wn = wid >> 1;
    const int ebase = blockIdx.x * 128;

    // prefetch first B chunk — overlaps index load + gather
    load_B_async(smb + OFF_BHI, smb + OFF_BLO, g_eBhi4, g_eBlo4, tid);

    if (tid < 128) {
        int e = ebase + tid;
        long long s = 0, dd = 0;
        if (e < E_EDGES) {
            if (g_idx64) {
                const long long* p = (const long long*)EI;
                s = p[e]; dd = p[E_EDGES + e];
            } else {
                const int* p = (const int*)EI;
                s = p[e]; dd = p[E_EDGES + e];
            }
        }
        ssrc[tid] = min(max((int)s, 0), N_NODES - 1);
        sdst[tid] = min(max((int)dd, 0), N_NODES - 1);
    }
    __syncthreads();

    // --- stage A: gather U[src]+V[dst]+b1, relu, split, full K=256 ---
    {
        const int lrow = tid >> 3;
        const int lk = (tid & 7) * 4;
        #pragma unroll 1
        for (int s = 0; s < 4; s++) {
            int row = s * 32 + lrow;
            const float* Ur = g_UV + (size_t)ssrc[row] * 512;
            const float* Vr = g_UV + (size_t)sdst[row] * 512 + 256;
            char* ah = sm + OFF_AHI + row * PITCH_A;
            char* al = sm + OFF_ALO + row * PITCH_A;
            #pragma unroll
            for (int i = 0; i < 8; i++) {
                int k = lk + i * 32;
                float4 u4 = *(const float4*)(Ur + k);
                float4 v4 = *(const float4*)(Vr + k);
                float4 c4 = *(const float4*)(b1 + k);
                float h0 = fmaxf(u4.x + v4.x + c4.x, 0.f);
                float h1 = fmaxf(u4.y + v4.y + c4.y, 0.f);
                float h2 = fmaxf(u4.z + v4.z + c4.z, 0.f);
                float h3 = fmaxf(u4.w + v4.w + c4.w, 0.f);
                uint32_t H0, L0, H1, L1;
                split2(h0, h1, H0, L0);
                split2(h2, h3, H1, L1);
                *(uint2*)(ah + k * 2) = make_uint2(H0, H1);
                *(uint2*)(al + k * 2) = make_uint2(L0, L1);
            }
        }
    }

    const uint32_t aHi = a_lane_base(smb + OFF_AHI, wm, lane);
    const uint32_t aLo = a_lane_base(smb + OFF_ALO, wm, lane);
    const uint32_t bHi = b_lane_base(smb + OFF_BHI, wn, lane);
    const uint32_t bLo = b_lane_base(smb + OFF_BLO, wn, lane);
    float* stg = (float*)(sm + OFF_BHI);

    float d[4][4][4];
    #pragma unroll
    for (int f = 0; f < 4; f++)
        #pragma unroll
        for (int g = 0; g < 4; g++)
            #pragma unroll
            for (int c = 0; c < 4; c++) d[f][g][c] = 0.f;

    #pragma unroll 1
    for (int kc = 0; kc < 2; kc++) {
        cp_wait0();
        __syncthreads();
        mma_chunk(d, aHi + kc * 256, aLo + kc * 256, bHi, bLo);
        __syncthreads();
        if (kc == 0)
            load_B_async(smb + OFF_BHI, smb + OFF_BLO,
                         g_eBhi4 + CHUNK_U4, g_eBlo4 + CHUNK_U4, tid);
    }

    // --- staged, coalesced epilogue with fused b2 ---
    stage_acc(stg, d, wm, wn, lane);
    __syncthreads();
    {
        const int c = (tid & 31) * 4;
        float4 bb = *(const float4*)(b2 + c);
        #pragma unroll
        for (int i = 0; i < 16; i++) {
            int idx = i * 256 + tid;
            int row = idx >> 5;
            int e = ebase + row;
            if (e < E_EDGES) {
                float4 v = *(const float4*)(stg + row * STG_PITCH + c);
                *(float4*)(out + (size_t)e * 128 + c) =
                    make_float4(v.x + bb.x, v.y + bb.y, v.z + bb.z, v.w + bb.w);
            }
        }
    }
}

// ---------------------------------------------------------------------------
// launch — inputs resolved by unique element counts
// ---------------------------------------------------------------------------
extern "C" void kernel_launch(void* const* d_in, const int* in_sizes, int n_in,
                              void* d_out, int out_size) {
    const float* z = nullptr;
    const void* ei = nullptr;
    const float* W1 = nullptr;
    const float* b1 = nullptr;
    const float* W2 = nullptr;
    const float* b2 = nullptr;
    for (int i = 0; i < n_in; i++) {
        switch (in_sizes[i]) {
            case 25600000: z = (const float*)d_in[i]; break;
            case 1000000:  ei = d_in[i];              break;
            case 131072:   W1 = (const float*)d_in[i]; break;
            case 256:      b1 = (const float*)d_in[i]; break;
            case 32768:    W2 = (const float*)d_in[i]; break;
            case 128:      b2 = (const float*)d_in[i]; break;
            default: break;
        }
    }
    float* out = (float*)d_out;

    cudaFuncSetAttribute(node_mma, cudaFuncAttributeMaxDynamicSharedMemorySize, SM_BYTES);
    cudaFuncSetAttribute(edge_mma, cudaFuncAttributeMaxDynamicSharedMemorySize, SM_BYTES);

    detect_kernel<<<1, 32>>>((const unsigned*)ei);
    prep_kernel<<<640, 256>>>(W1, W2);
    node_mma<<<(N_NODES + 127) / 128, 256, SM_BYTES>>>(z);
    edge_mma<<<(E_EDGES + 127) / 128, 256, SM_BYTES>>>(ei, b1, b2, out);
}